// round 13
// baseline (speedup 1.0000x reference)
#include <cuda_runtime.h>
#include <cstdint>
#include <float.h>

// Problem constants
#define B_ 64
#define T_ 2048
#define F_ 256
#define U_ 32

// ---------------------------------------------------------------------------
// Scratch (static device globals; no allocation allowed)
// ---------------------------------------------------------------------------
__device__ float         g_pot   [B_ * T_ * U_];   // 16 MB
__device__ float         g_states[B_ * T_ * U_];   // 16 MB
__device__ unsigned char g_bp    [B_ * T_ * U_];   //  4 MB
__device__ int           g_last  [B_];

// ---------------------------------------------------------------------------
// K1: potentials  pot[b,t,u] = dot(x[b,t,:], kernel[:,u]) + bias[u] (+bounds)
//   2 warps/block, 4 rows per warp-tile (quad). Per f-iter: 1 LDS.32 (kk) +
//   1 LDS.128 broadcast (x for 4 rows) + 4 FFMA — 4x fewer kk reads per row
//   than the Round-12 version (which was LDS-throughput-bound).
//   Staging: lane (r = lane&3, fb = lane>>2) loads x[row0+r][f0+fb*4..+3]
//   and scatters via 4 STS.32 at float-addr f*4+r (bank = (r+4f)%32 —
//   conflict-free). 40KB static smem.
// ---------------------------------------------------------------------------
#define K1_WARPS 2

__global__ void k1_pot(const float* __restrict__ x, const float* __restrict__ kern,
                       const float* __restrict__ bias, const float* __restrict__ lb,
                       const float* __restrict__ rb) {
    __shared__ __align__(16) float kk[F_ * U_];          // 32 KB: kk[f*32+u]
    __shared__ __align__(16) float xs[K1_WARPS][F_][4];  //  8 KB: [f][row]

    const int tid  = threadIdx.x;
    const int w    = tid >> 5;
    const int lane = tid & 31;

    for (int i = tid; i < F_ * U_; i += 32 * K1_WARPS) kk[i] = kern[i];
    const float bv  = bias[lane];
    const float lbv = lb[lane];
    const float rbv = rb[lane];
    __syncthreads();

    const int quadGlobal = blockIdx.x * K1_WARPS + w;
    const int nQuads     = gridDim.x * K1_WARPS;
    const int r  = lane & 3;        // row within quad this lane stages
    const int fb = lane >> 2;       // f-block (8 blocks of 4 floats per pass)

    for (int q = quadGlobal; q < (B_ * T_) / 4; q += nQuads) {
        const int row0 = q * 4;

        // Stage 4 rows f-major: 8 passes cover f = 0..255.
        #pragma unroll
        for (int p = 0; p < 8; p++) {
            const int f0 = p * 32 + fb * 4;
            float4 v = *(const float4*)(x + (size_t)(row0 + r) * F_ + f0);
            xs[w][f0 + 0][r] = v.x;
            xs[w][f0 + 1][r] = v.y;
            xs[w][f0 + 2][r] = v.z;
            xs[w][f0 + 3][r] = v.w;
        }
        __syncwarp();

        float a0 = 0.0f, a1 = 0.0f, a2 = 0.0f, a3 = 0.0f;
        #pragma unroll 8
        for (int f = 0; f < F_; f++) {
            float  kv = kk[f * U_ + lane];
            float4 xv = *(const float4*)&xs[w][f][0];
            a0 = fmaf(xv.x, kv, a0);
            a1 = fmaf(xv.y, kv, a1);
            a2 = fmaf(xv.z, kv, a2);
            a3 = fmaf(xv.w, kv, a3);
        }

        float acc[4] = {a0, a1, a2, a3};
        #pragma unroll
        for (int i = 0; i < 4; i++) {
            int   row = row0 + i;
            int   t   = row & (T_ - 1);
            float val = acc[i] + bv;
            if (t == 0)      val += lbv;
            if (t == T_ - 1) val += rbv;
            g_pot[(size_t)row * U_ + lane] = val;
        }
        __syncwarp();
    }
}

// ---------------------------------------------------------------------------
// K2: Viterbi forward (max only). One warp per batch. Chunk-of-8 unrolled
//   prefetch pipeline (compile-time indices — keeps pf in registers).
// ---------------------------------------------------------------------------
__device__ __forceinline__ void k2_step(int t, float pv, float (&st)[2][U_],
                                        const float (&cT)[U_], float* __restrict__ sb,
                                        int u, float& s_out) {
    const int wr = t & 1, rd = wr ^ 1;
    float c[U_];
    #pragma unroll
    for (int qd = 0; qd < 8; qd++) {
        float4 a4 = *(const float4*)&st[rd][qd * 4];
        c[qd * 4 + 0] = a4.x + cT[qd * 4 + 0];
        c[qd * 4 + 1] = a4.y + cT[qd * 4 + 1];
        c[qd * 4 + 2] = a4.z + cT[qd * 4 + 2];
        c[qd * 4 + 3] = a4.w + cT[qd * 4 + 3];
    }
    #pragma unroll
    for (int s2 = 16; s2 >= 1; s2 >>= 1)
        #pragma unroll
        for (int i = 0; i < 16; i++)
            if (i < s2) c[i] = fmaxf(c[i], c[i + s2]);

    const float ns = c[0] + pv;
    st[wr][u] = ns;
    sb[(size_t)t * U_ + u] = ns;
    s_out = ns;
    __syncwarp();
}

__global__ void k2_forward(const float* __restrict__ chain) {
    const int b = blockIdx.x;
    const int u = threadIdx.x;

    __shared__ __align__(16) float st[2][U_];

    float cT[U_];
    #pragma unroll
    for (int v = 0; v < U_; v++) cT[v] = chain[v * U_ + u];

    const float* pb = g_pot    + (size_t)b * T_ * U_;
    float*       sb = g_states + (size_t)b * T_ * U_;

    float s = pb[u];
    sb[u] = s;
    st[0][u] = s;
    __syncwarp();

    float pf[8];
    #pragma unroll
    for (int i = 0; i < 8; i++) pf[i] = pb[(size_t)(1 + i) * U_ + u];

    int t = 1;
    for (; t + 8 <= T_; t += 8) {
        #pragma unroll
        for (int k = 0; k < 8; k++) {
            k2_step(t + k, pf[k], st, cT, sb, u, s);
            if (t + k + 8 < T_) pf[k] = pb[(size_t)(t + k + 8) * U_ + u];
        }
    }
    #pragma unroll
    for (int k = 0; k < 7; k++) {
        k2_step(t + k, pf[k], st, cT, sb, u, s);
    }

    float m = s;
    #pragma unroll
    for (int o = 16; o; o >>= 1) m = fmaxf(m, __shfl_xor_sync(0xffffffffu, m, o));
    unsigned mask = __ballot_sync(0xffffffffu, s == m);
    if (u == 0) {
        int ff = __ffs(mask);
        g_last[b] = (ff > 0) ? (ff - 1) : 0;
    }
}

// ---------------------------------------------------------------------------
// K3: backpointer recompute (parallel over all (b,t), t>=1)
//   bp[b,t,u] = argmax_v(state[b,t-1,v] + chain[v,u])  (strict '>' ascending
//   v = first-index ties, matching jnp.argmax).
// ---------------------------------------------------------------------------
__global__ void k3_bp(const float* __restrict__ chain) {
    const int lane = threadIdx.x & 31;
    const int wInB = threadIdx.x >> 5;
    const int warp = (blockIdx.x * blockDim.x + threadIdx.x) >> 5;
    const int nwarp = (gridDim.x * blockDim.x) >> 5;

    __shared__ __align__(16) float srow[8][U_];

    float cT[U_];
    #pragma unroll
    for (int v = 0; v < U_; v++) cT[v] = chain[v * U_ + lane];

    const int total = B_ * (T_ - 1);
    for (int i = warp; i < total; i += nwarp) {
        const int b = i / (T_ - 1);
        const int t = i % (T_ - 1) + 1;
        float sv = g_states[((size_t)b * T_ + (t - 1)) * U_ + lane];
        srow[wInB][lane] = sv;
        __syncwarp();

        float best = srow[wInB][0] + cT[0];
        int   bi = 0;
        #pragma unroll
        for (int v = 1; v < U_; v++) {
            float cc = srow[wInB][v] + cT[v];
            if (cc > best) { best = cc; bi = v; }
        }
        g_bp[((size_t)b * T_ + t) * U_ + lane] = (unsigned char)bi;
        __syncwarp();
    }
}

// ---------------------------------------------------------------------------
// K4: parallel backtrack via suffix composition of bp functions.
//   One block per batch, 32 warps of 64-step chunks. OUTPUT IS FLOAT32.
// ---------------------------------------------------------------------------
__global__ void k4_back(float* __restrict__ out) {
    __shared__ unsigned char C[32][32];
    __shared__ int ev[32];

    const int b    = blockIdx.x;
    const int tid  = threadIdx.x;
    const int w    = tid >> 5;
    const int lane = tid & 31;

    const int tstart = w * 64 + 1;
    const int tend   = min(w * 64 + 64, T_ - 1);

    const unsigned char* bpb = g_bp + (size_t)b * T_ * U_;

    int f = lane;
    for (int t = tend; t >= tstart; t--) {
        int g = bpb[(size_t)t * U_ + lane] & 31;
        f = __shfl_sync(0xffffffffu, g, f);
    }
    C[w][lane] = (unsigned char)f;
    __syncthreads();

    if (tid == 0) {
        int v = g_last[b] & 31;
        ev[31] = v;
        for (int w2 = 30; w2 >= 0; w2--) {
            v = C[w2 + 1][v] & 31;
            ev[w2] = v;
        }
        out[b * T_ + (T_ - 1)] = (float)(g_last[b] & 31);
    }
    __syncthreads();

    const int e = ev[w];
    f = lane;
    for (int t = tend; t >= tstart; t--) {
        int g = bpb[(size_t)t * U_ + lane] & 31;
        f = __shfl_sync(0xffffffffu, g, f);
        int tag = __shfl_sync(0xffffffffu, f, e);
        if (lane == 0) out[b * T_ + (t - 1)] = (float)tag;
    }
}

// ---------------------------------------------------------------------------
// Launch — RANK-BASED input identification (unit-free). Stable sort keeps
// the three equal-size U-vectors in original relative order:
// (bias, left_boundary, right_boundary).
// ---------------------------------------------------------------------------
extern "C" void kernel_launch(void* const* d_in, const int* in_sizes, int n_in,
                              void* d_out, int out_size) {
    int idx[16];
    int n = (n_in < 16) ? n_in : 16;
    for (int i = 0; i < n; i++) idx[i] = i;
    for (int i = 1; i < n; i++) {                 // stable insertion sort, desc
        int cur = idx[i];
        int j = i - 1;
        while (j >= 0 && in_sizes[idx[j]] < in_sizes[cur]) {
            idx[j + 1] = idx[j];
            j--;
        }
        idx[j + 1] = cur;
    }

    const float* x     = (const float*)d_in[idx[0]];
    const float* kern  = (const float*)d_in[idx[1]];
    const float* chain = (const float*)d_in[idx[2]];
    const float* bias  = (const float*)d_in[idx[3]];
    const float* lb    = (const float*)d_in[idx[4]];
    const float* rb    = (const float*)d_in[idx[5]];
    float* out = (float*)d_out;

    // 32768 quads, 2 warps per block -> 16384 blocks.
    k1_pot    <<<16384, 32 * K1_WARPS>>>(x, kern, bias, lb, rb);
    k2_forward<<<B_, 32>>>(chain);
    k3_bp     <<<1024, 256>>>(chain);
    k4_back   <<<B_, 1024>>>(out);
}

// round 14
// speedup vs baseline: 1.2806x; 1.2806x over previous
#include <cuda_runtime.h>
#include <cstdint>
#include <float.h>

// Problem constants
#define B_ 64
#define T_ 2048
#define F_ 256
#define U_ 32

// ---------------------------------------------------------------------------
// Scratch (static device globals; no allocation allowed)
// ---------------------------------------------------------------------------
__device__ float         g_pot   [B_ * T_ * U_];   // 16 MB
__device__ float         g_states[B_ * T_ * U_];   // 16 MB
__device__ unsigned char g_bp    [B_ * T_ * U_];   //  4 MB
__device__ int           g_last  [B_];

// ---------------------------------------------------------------------------
// K1: potentials  pot[b,t,u] = dot(x[b,t,:], kernel[:,u]) + bias[u] (+bounds)
//   2 warps/block, 4 rows per warp-tile (quad), grid-stride over quads.
//   Per f-iter: 1 LDS.32 (kk) + 1 LDS.128 broadcast (x, 4 rows) + 4 FFMA.
//   LAUNCHED WITH 2048 BLOCKS (Round-13 bug: 16384 blocks gave each block
//   only 8 rows per 32KB kk-tile load — the tile load dominated).
//   Now: 8 quads/warp = 64 rows/block per kk load.
// ---------------------------------------------------------------------------
#define K1_WARPS 2

__global__ void k1_pot(const float* __restrict__ x, const float* __restrict__ kern,
                       const float* __restrict__ bias, const float* __restrict__ lb,
                       const float* __restrict__ rb) {
    __shared__ __align__(16) float kk[F_ * U_];          // 32 KB: kk[f*32+u]
    __shared__ __align__(16) float xs[K1_WARPS][F_][4];  //  8 KB: [f][row]

    const int tid  = threadIdx.x;
    const int w    = tid >> 5;
    const int lane = tid & 31;

    for (int i = tid; i < F_ * U_; i += 32 * K1_WARPS) kk[i] = kern[i];
    const float bv  = bias[lane];
    const float lbv = lb[lane];
    const float rbv = rb[lane];
    __syncthreads();

    const int quadGlobal = blockIdx.x * K1_WARPS + w;
    const int nQuads     = gridDim.x * K1_WARPS;
    const int r  = lane & 3;        // row within quad this lane stages
    const int fb = lane >> 2;       // f-block (8 blocks of 4 floats per pass)

    for (int q = quadGlobal; q < (B_ * T_) / 4; q += nQuads) {
        const int row0 = q * 4;

        // Stage 4 rows f-major: 8 passes cover f = 0..255.
        #pragma unroll
        for (int p = 0; p < 8; p++) {
            const int f0 = p * 32 + fb * 4;
            float4 v = *(const float4*)(x + (size_t)(row0 + r) * F_ + f0);
            xs[w][f0 + 0][r] = v.x;
            xs[w][f0 + 1][r] = v.y;
            xs[w][f0 + 2][r] = v.z;
            xs[w][f0 + 3][r] = v.w;
        }
        __syncwarp();

        float a0 = 0.0f, a1 = 0.0f, a2 = 0.0f, a3 = 0.0f;
        #pragma unroll 8
        for (int f = 0; f < F_; f++) {
            float  kv = kk[f * U_ + lane];
            float4 xv = *(const float4*)&xs[w][f][0];
            a0 = fmaf(xv.x, kv, a0);
            a1 = fmaf(xv.y, kv, a1);
            a2 = fmaf(xv.z, kv, a2);
            a3 = fmaf(xv.w, kv, a3);
        }

        float acc[4] = {a0, a1, a2, a3};
        #pragma unroll
        for (int i = 0; i < 4; i++) {
            int   row = row0 + i;
            int   t   = row & (T_ - 1);
            float val = acc[i] + bv;
            if (t == 0)      val += lbv;
            if (t == T_ - 1) val += rbv;
            g_pot[(size_t)row * U_ + lane] = val;
        }
        __syncwarp();
    }
}

// ---------------------------------------------------------------------------
// K2: Viterbi forward (max only). One warp per batch. Chunk-of-8 unrolled
//   prefetch pipeline (compile-time indices — keeps pf in registers).
// ---------------------------------------------------------------------------
__device__ __forceinline__ void k2_step(int t, float pv, float (&st)[2][U_],
                                        const float (&cT)[U_], float* __restrict__ sb,
                                        int u, float& s_out) {
    const int wr = t & 1, rd = wr ^ 1;
    float c[U_];
    #pragma unroll
    for (int qd = 0; qd < 8; qd++) {
        float4 a4 = *(const float4*)&st[rd][qd * 4];
        c[qd * 4 + 0] = a4.x + cT[qd * 4 + 0];
        c[qd * 4 + 1] = a4.y + cT[qd * 4 + 1];
        c[qd * 4 + 2] = a4.z + cT[qd * 4 + 2];
        c[qd * 4 + 3] = a4.w + cT[qd * 4 + 3];
    }
    #pragma unroll
    for (int s2 = 16; s2 >= 1; s2 >>= 1)
        #pragma unroll
        for (int i = 0; i < 16; i++)
            if (i < s2) c[i] = fmaxf(c[i], c[i + s2]);

    const float ns = c[0] + pv;
    st[wr][u] = ns;
    sb[(size_t)t * U_ + u] = ns;
    s_out = ns;
    __syncwarp();
}

__global__ void k2_forward(const float* __restrict__ chain) {
    const int b = blockIdx.x;
    const int u = threadIdx.x;

    __shared__ __align__(16) float st[2][U_];

    float cT[U_];
    #pragma unroll
    for (int v = 0; v < U_; v++) cT[v] = chain[v * U_ + u];

    const float* pb = g_pot    + (size_t)b * T_ * U_;
    float*       sb = g_states + (size_t)b * T_ * U_;

    float s = pb[u];
    sb[u] = s;
    st[0][u] = s;
    __syncwarp();

    float pf[8];
    #pragma unroll
    for (int i = 0; i < 8; i++) pf[i] = pb[(size_t)(1 + i) * U_ + u];

    int t = 1;
    for (; t + 8 <= T_; t += 8) {
        #pragma unroll
        for (int k = 0; k < 8; k++) {
            k2_step(t + k, pf[k], st, cT, sb, u, s);
            if (t + k + 8 < T_) pf[k] = pb[(size_t)(t + k + 8) * U_ + u];
        }
    }
    #pragma unroll
    for (int k = 0; k < 7; k++) {
        k2_step(t + k, pf[k], st, cT, sb, u, s);
    }

    float m = s;
    #pragma unroll
    for (int o = 16; o; o >>= 1) m = fmaxf(m, __shfl_xor_sync(0xffffffffu, m, o));
    unsigned mask = __ballot_sync(0xffffffffu, s == m);
    if (u == 0) {
        int ff = __ffs(mask);
        g_last[b] = (ff > 0) ? (ff - 1) : 0;
    }
}

// ---------------------------------------------------------------------------
// K3: backpointer recompute (parallel over all (b,t), t>=1)
//   bp[b,t,u] = argmax_v(state[b,t-1,v] + chain[v,u])  (strict '>' ascending
//   v = first-index ties, matching jnp.argmax).
// ---------------------------------------------------------------------------
__global__ void k3_bp(const float* __restrict__ chain) {
    const int lane = threadIdx.x & 31;
    const int wInB = threadIdx.x >> 5;
    const int warp = (blockIdx.x * blockDim.x + threadIdx.x) >> 5;
    const int nwarp = (gridDim.x * blockDim.x) >> 5;

    __shared__ __align__(16) float srow[8][U_];

    float cT[U_];
    #pragma unroll
    for (int v = 0; v < U_; v++) cT[v] = chain[v * U_ + lane];

    const int total = B_ * (T_ - 1);
    for (int i = warp; i < total; i += nwarp) {
        const int b = i / (T_ - 1);
        const int t = i % (T_ - 1) + 1;
        float sv = g_states[((size_t)b * T_ + (t - 1)) * U_ + lane];
        srow[wInB][lane] = sv;
        __syncwarp();

        float best = srow[wInB][0] + cT[0];
        int   bi = 0;
        #pragma unroll
        for (int v = 1; v < U_; v++) {
            float cc = srow[wInB][v] + cT[v];
            if (cc > best) { best = cc; bi = v; }
        }
        g_bp[((size_t)b * T_ + t) * U_ + lane] = (unsigned char)bi;
        __syncwarp();
    }
}

// ---------------------------------------------------------------------------
// K4: parallel backtrack via suffix composition of bp functions.
//   One block per batch, 32 warps of 64-step chunks. OUTPUT IS FLOAT32.
// ---------------------------------------------------------------------------
__global__ void k4_back(float* __restrict__ out) {
    __shared__ unsigned char C[32][32];
    __shared__ int ev[32];

    const int b    = blockIdx.x;
    const int tid  = threadIdx.x;
    const int w    = tid >> 5;
    const int lane = tid & 31;

    const int tstart = w * 64 + 1;
    const int tend   = min(w * 64 + 64, T_ - 1);

    const unsigned char* bpb = g_bp + (size_t)b * T_ * U_;

    int f = lane;
    for (int t = tend; t >= tstart; t--) {
        int g = bpb[(size_t)t * U_ + lane] & 31;
        f = __shfl_sync(0xffffffffu, g, f);
    }
    C[w][lane] = (unsigned char)f;
    __syncthreads();

    if (tid == 0) {
        int v = g_last[b] & 31;
        ev[31] = v;
        for (int w2 = 30; w2 >= 0; w2--) {
            v = C[w2 + 1][v] & 31;
            ev[w2] = v;
        }
        out[b * T_ + (T_ - 1)] = (float)(g_last[b] & 31);
    }
    __syncthreads();

    const int e = ev[w];
    f = lane;
    for (int t = tend; t >= tstart; t--) {
        int g = bpb[(size_t)t * U_ + lane] & 31;
        f = __shfl_sync(0xffffffffu, g, f);
        int tag = __shfl_sync(0xffffffffu, f, e);
        if (lane == 0) out[b * T_ + (t - 1)] = (float)tag;
    }
}

// ---------------------------------------------------------------------------
// Launch — RANK-BASED input identification (unit-free). Stable sort keeps
// the three equal-size U-vectors in original relative order:
// (bias, left_boundary, right_boundary).
// ---------------------------------------------------------------------------
extern "C" void kernel_launch(void* const* d_in, const int* in_sizes, int n_in,
                              void* d_out, int out_size) {
    int idx[16];
    int n = (n_in < 16) ? n_in : 16;
    for (int i = 0; i < n; i++) idx[i] = i;
    for (int i = 1; i < n; i++) {                 // stable insertion sort, desc
        int cur = idx[i];
        int j = i - 1;
        while (j >= 0 && in_sizes[idx[j]] < in_sizes[cur]) {
            idx[j + 1] = idx[j];
            j--;
        }
        idx[j + 1] = cur;
    }

    const float* x     = (const float*)d_in[idx[0]];
    const float* kern  = (const float*)d_in[idx[1]];
    const float* chain = (const float*)d_in[idx[2]];
    const float* bias  = (const float*)d_in[idx[3]];
    const float* rb_   = (const float*)d_in[idx[5]];
    const float* lb    = (const float*)d_in[idx[4]];
    float* out = (float*)d_out;

    // 32768 quads, 2 warps/block, 2048 blocks -> 8 quads per warp
    // (64 rows per 32KB kk-tile load — amortization restored).
    k1_pot    <<<2048, 32 * K1_WARPS>>>(x, kern, bias, lb, rb_);
    k2_forward<<<B_, 32>>>(chain);
    k3_bp     <<<1024, 256>>>(chain);
    k4_back   <<<B_, 1024>>>(out);
}

// round 15
// speedup vs baseline: 1.2809x; 1.0002x over previous
#include <cuda_runtime.h>
#include <cstdint>
#include <float.h>

// Problem constants
#define B_ 64
#define T_ 2048
#define F_ 256
#define U_ 32

// ---------------------------------------------------------------------------
// Scratch (static device globals; no allocation allowed)
// ---------------------------------------------------------------------------
__device__ float         g_pot   [B_ * T_ * U_];   // 16 MB
__device__ float         g_states[B_ * T_ * U_];   // 16 MB
__device__ unsigned char g_bp    [B_ * T_ * U_];   //  4 MB
__device__ int           g_last  [B_];

// ---------------------------------------------------------------------------
// f32x2 helpers (Blackwell packed math; pack/unpack are register-pair movs)
// ---------------------------------------------------------------------------
__device__ __forceinline__ unsigned long long pack2(float lo, float hi) {
    unsigned long long r;
    asm("mov.b64 %0, {%1, %2};" : "=l"(r) : "f"(lo), "f"(hi));
    return r;
}
__device__ __forceinline__ unsigned long long add2(unsigned long long a,
                                                   unsigned long long b) {
    unsigned long long r;
    asm("add.rn.f32x2 %0, %1, %2;" : "=l"(r) : "l"(a), "l"(b));
    return r;
}
__device__ __forceinline__ float pmax2(unsigned long long p) {
    float lo, hi;
    asm("mov.b64 {%0, %1}, %2;" : "=f"(lo), "=f"(hi) : "l"(p));
    return fmaxf(lo, hi);
}

// ---------------------------------------------------------------------------
// K1: potentials  pot[b,t,u] = dot(x[b,t,:], kernel[:,u]) + bias[u] (+bounds)
//   2 warps/block, 4 rows/warp-tile, 8 quads per warp (grid-stride), so each
//   32KB kk-tile load is amortized over 64 rows per block.
// ---------------------------------------------------------------------------
#define K1_WARPS 2

__global__ void k1_pot(const float* __restrict__ x, const float* __restrict__ kern,
                       const float* __restrict__ bias, const float* __restrict__ lb,
                       const float* __restrict__ rb) {
    __shared__ __align__(16) float kk[F_ * U_];          // 32 KB: kk[f*32+u]
    __shared__ __align__(16) float xs[K1_WARPS][F_][4];  //  8 KB: [f][row]

    const int tid  = threadIdx.x;
    const int w    = tid >> 5;
    const int lane = tid & 31;

    for (int i = tid; i < F_ * U_; i += 32 * K1_WARPS) kk[i] = kern[i];
    const float bv  = bias[lane];
    const float lbv = lb[lane];
    const float rbv = rb[lane];
    __syncthreads();

    const int quadGlobal = blockIdx.x * K1_WARPS + w;
    const int nQuads     = gridDim.x * K1_WARPS;
    const int r  = lane & 3;
    const int fb = lane >> 2;

    for (int q = quadGlobal; q < (B_ * T_) / 4; q += nQuads) {
        const int row0 = q * 4;

        #pragma unroll
        for (int p = 0; p < 8; p++) {
            const int f0 = p * 32 + fb * 4;
            float4 v = *(const float4*)(x + (size_t)(row0 + r) * F_ + f0);
            xs[w][f0 + 0][r] = v.x;
            xs[w][f0 + 1][r] = v.y;
            xs[w][f0 + 2][r] = v.z;
            xs[w][f0 + 3][r] = v.w;
        }
        __syncwarp();

        float a0 = 0.0f, a1 = 0.0f, a2 = 0.0f, a3 = 0.0f;
        #pragma unroll 8
        for (int f = 0; f < F_; f++) {
            float  kv = kk[f * U_ + lane];
            float4 xv = *(const float4*)&xs[w][f][0];
            a0 = fmaf(xv.x, kv, a0);
            a1 = fmaf(xv.y, kv, a1);
            a2 = fmaf(xv.z, kv, a2);
            a3 = fmaf(xv.w, kv, a3);
        }

        float acc[4] = {a0, a1, a2, a3};
        #pragma unroll
        for (int i = 0; i < 4; i++) {
            int   row = row0 + i;
            int   t   = row & (T_ - 1);
            float val = acc[i] + bv;
            if (t == 0)      val += lbv;
            if (t == T_ - 1) val += rbv;
            g_pot[(size_t)row * U_ + lane] = val;
        }
        __syncwarp();
    }
}

// ---------------------------------------------------------------------------
// K2: Viterbi forward (max only). One warp per batch. Chunk-of-8 unrolled
//   prefetch pipeline. Step math packed: 16 add.rn.f32x2 replace 32 FADDs;
//   max tree reshaped into fmax3-fusable triples (FMNMX3 on sm_103a).
//   Max is exact, so downstream argmax (K3) is unaffected.
// ---------------------------------------------------------------------------
__device__ __forceinline__ void k2_step(int t, float pv, float (&st)[2][U_],
                                        const unsigned long long (&cT2)[16],
                                        float* __restrict__ sb,
                                        int u, float& s_out) {
    const int wr = t & 1, rd = wr ^ 1;

    float g[8];
    #pragma unroll
    for (int qd = 0; qd < 8; qd++) {
        float4 a4 = *(const float4*)&st[rd][qd * 4];
        unsigned long long c01 = add2(pack2(a4.x, a4.y), cT2[qd * 2 + 0]);
        unsigned long long c23 = add2(pack2(a4.z, a4.w), cT2[qd * 2 + 1]);
        g[qd] = fmaxf(pmax2(c01), pmax2(c23));
    }
    // 8 -> 1 in fmax3-friendly triples (ptxas fuses fmaxf(fmaxf(a,b),c)).
    float m0 = fmaxf(fmaxf(g[0], g[1]), g[2]);
    float m1 = fmaxf(fmaxf(g[3], g[4]), g[5]);
    float m2 = fmaxf(g[6], g[7]);
    const float ns = fmaxf(fmaxf(m0, m1), m2) + pv;

    st[wr][u] = ns;
    sb[(size_t)t * U_ + u] = ns;
    s_out = ns;
    __syncwarp();
}

__global__ void k2_forward(const float* __restrict__ chain) {
    const int b = blockIdx.x;
    const int u = threadIdx.x;

    __shared__ __align__(16) float st[2][U_];

    unsigned long long cT2[16];          // packed pairs (chain[2j][u], chain[2j+1][u])
    #pragma unroll
    for (int j = 0; j < 16; j++)
        cT2[j] = pack2(chain[(2 * j) * U_ + u], chain[(2 * j + 1) * U_ + u]);

    const float* pb = g_pot    + (size_t)b * T_ * U_;
    float*       sb = g_states + (size_t)b * T_ * U_;

    float s = pb[u];
    sb[u] = s;
    st[0][u] = s;
    __syncwarp();

    float pf[8];
    #pragma unroll
    for (int i = 0; i < 8; i++) pf[i] = pb[(size_t)(1 + i) * U_ + u];

    int t = 1;
    for (; t + 8 <= T_; t += 8) {
        #pragma unroll
        for (int k = 0; k < 8; k++) {
            k2_step(t + k, pf[k], st, cT2, sb, u, s);
            if (t + k + 8 < T_) pf[k] = pb[(size_t)(t + k + 8) * U_ + u];
        }
    }
    #pragma unroll
    for (int k = 0; k < 7; k++) {
        k2_step(t + k, pf[k], st, cT2, sb, u, s);
    }

    float m = s;
    #pragma unroll
    for (int o = 16; o; o >>= 1) m = fmaxf(m, __shfl_xor_sync(0xffffffffu, m, o));
    unsigned mask = __ballot_sync(0xffffffffu, s == m);
    if (u == 0) {
        int ff = __ffs(mask);
        g_last[b] = (ff > 0) ? (ff - 1) : 0;
    }
}

// ---------------------------------------------------------------------------
// K3: backpointer recompute (parallel over all (b,t), t>=1)
//   bp[b,t,u] = argmax_v(state[b,t-1,v] + chain[v,u])  (strict '>' ascending
//   v = first-index ties, matching jnp.argmax).
// ---------------------------------------------------------------------------
__global__ void k3_bp(const float* __restrict__ chain) {
    const int lane = threadIdx.x & 31;
    const int wInB = threadIdx.x >> 5;
    const int warp = (blockIdx.x * blockDim.x + threadIdx.x) >> 5;
    const int nwarp = (gridDim.x * blockDim.x) >> 5;

    __shared__ __align__(16) float srow[8][U_];

    float cT[U_];
    #pragma unroll
    for (int v = 0; v < U_; v++) cT[v] = chain[v * U_ + lane];

    const int total = B_ * (T_ - 1);
    for (int i = warp; i < total; i += nwarp) {
        const int b = i / (T_ - 1);
        const int t = i % (T_ - 1) + 1;
        float sv = g_states[((size_t)b * T_ + (t - 1)) * U_ + lane];
        srow[wInB][lane] = sv;
        __syncwarp();

        float best = srow[wInB][0] + cT[0];
        int   bi = 0;
        #pragma unroll
        for (int v = 1; v < U_; v++) {
            float cc = srow[wInB][v] + cT[v];
            if (cc > best) { best = cc; bi = v; }
        }
        g_bp[((size_t)b * T_ + t) * U_ + lane] = (unsigned char)bi;
        __syncwarp();
    }
}

// ---------------------------------------------------------------------------
// K4: parallel backtrack via suffix composition of bp functions.
//   One block per batch, 32 warps of 64-step chunks. OUTPUT IS FLOAT32.
// ---------------------------------------------------------------------------
__global__ void k4_back(float* __restrict__ out) {
    __shared__ unsigned char C[32][32];
    __shared__ int ev[32];

    const int b    = blockIdx.x;
    const int tid  = threadIdx.x;
    const int w    = tid >> 5;
    const int lane = tid & 31;

    const int tstart = w * 64 + 1;
    const int tend   = min(w * 64 + 64, T_ - 1);

    const unsigned char* bpb = g_bp + (size_t)b * T_ * U_;

    int f = lane;
    for (int t = tend; t >= tstart; t--) {
        int g = bpb[(size_t)t * U_ + lane] & 31;
        f = __shfl_sync(0xffffffffu, g, f);
    }
    C[w][lane] = (unsigned char)f;
    __syncthreads();

    if (tid == 0) {
        int v = g_last[b] & 31;
        ev[31] = v;
        for (int w2 = 30; w2 >= 0; w2--) {
            v = C[w2 + 1][v] & 31;
            ev[w2] = v;
        }
        out[b * T_ + (T_ - 1)] = (float)(g_last[b] & 31);
    }
    __syncthreads();

    const int e = ev[w];
    f = lane;
    for (int t = tend; t >= tstart; t--) {
        int g = bpb[(size_t)t * U_ + lane] & 31;
        f = __shfl_sync(0xffffffffu, g, f);
        int tag = __shfl_sync(0xffffffffu, f, e);
        if (lane == 0) out[b * T_ + (t - 1)] = (float)tag;
    }
}

// ---------------------------------------------------------------------------
// Launch — RANK-BASED input identification (unit-free). Stable sort keeps
// the three equal-size U-vectors in original relative order:
// (bias, left_boundary, right_boundary).
// ---------------------------------------------------------------------------
extern "C" void kernel_launch(void* const* d_in, const int* in_sizes, int n_in,
                              void* d_out, int out_size) {
    int idx[16];
    int n = (n_in < 16) ? n_in : 16;
    for (int i = 0; i < n; i++) idx[i] = i;
    for (int i = 1; i < n; i++) {                 // stable insertion sort, desc
        int cur = idx[i];
        int j = i - 1;
        while (j >= 0 && in_sizes[idx[j]] < in_sizes[cur]) {
            idx[j + 1] = idx[j];
            j--;
        }
        idx[j + 1] = cur;
    }

    const float* x     = (const float*)d_in[idx[0]];
    const float* kern  = (const float*)d_in[idx[1]];
    const float* chain = (const float*)d_in[idx[2]];
    const float* bias  = (const float*)d_in[idx[3]];
    const float* lb    = (const float*)d_in[idx[4]];
    const float* rb    = (const float*)d_in[idx[5]];
    float* out = (float*)d_out;

    k1_pot    <<<2048, 32 * K1_WARPS>>>(x, kern, bias, lb, rb);
    k2_forward<<<B_, 32>>>(chain);
    k3_bp     <<<1024, 256>>>(chain);
    k4_back   <<<B_, 1024>>>(out);
}